// round 1
// baseline (speedup 1.0000x reference)
#include <cuda_runtime.h>
#include <math.h>

// Problem dims
#define B     4096
#define F     4096
#define V     1024
#define E     512
#define H     1024
#define L     30
#define G4H   4096     // 4*H
#define KC    1536     // E + H
#define BOUND 1023
#define LP1   31       // L+1
#define NDIS  3

// ---------------- device scratch (no allocations allowed) ----------------
__device__ float g_c[B * H];              // LSTM cell state
__device__ float g_xh[B * KC];            // concat [x | h] activation buffer
__device__ float g_gates[B * G4H];        // LSTM pre-activations
__device__ float g_scores[B * V];
__device__ int   g_tok[B];
__device__ int   g_sl[B];
__device__ float g_vl[B];
__device__ int   g_m[B * LP1];
__device__ float g_Wc[G4H * KC];          // sender concat weights
__device__ float g_bc[G4H];
__device__ float g_WcR[G4H * KC];         // receiver concat weights
__device__ float g_bcR[G4H];
__device__ float g_nwc[V];
__device__ float g_r[B * F];
__device__ float g_loss[B];
__device__ float g_acc[B];
__device__ float g_wcnt[V];

// ---------------- generic fp32 GEMM: C[M,N] = A[M,K] * W[N,K]^T + bias ----------------
// 128x128 block tile, K-tile 16, 256 threads, 8x8 per thread (2x2 quadrant mapping).
// Requires: M%128==0, N%128==0, K%16==0, pointers 16B aligned, lda/ldw/ldc %4==0.
__global__ __launch_bounds__(256, 2)
void sgemm_tn(const float* __restrict__ A, int lda,
              const float* __restrict__ W, int ldw,
              float* __restrict__ C, int ldc,
              const float* __restrict__ bias, int K)
{
    __shared__ float As[16][132];
    __shared__ float Bs[16][132];
    const int tid = threadIdx.x;
    const int tx = tid & 15;     // 0..15  -> N quadrant offsets
    const int ty = tid >> 4;     // 0..15  -> M quadrant offsets

    const float* Ab = A + (size_t)blockIdx.y * 128 * lda;
    const float* Wb = W + (size_t)blockIdx.x * 128 * ldw;

    float acc[8][8];
#pragma unroll
    for (int i = 0; i < 8; i++)
#pragma unroll
        for (int j = 0; j < 8; j++) acc[i][j] = 0.f;

    const int r0 = tid >> 2;           // 0..63 row within tile
    const int kq = (tid & 3) << 2;     // 0,4,8,12 k offset

    for (int kt = 0; kt < K; kt += 16) {
        float4 a0 = *(const float4*)(Ab + (size_t)r0 * lda + kt + kq);
        float4 a1 = *(const float4*)(Ab + (size_t)(r0 + 64) * lda + kt + kq);
        float4 b0 = *(const float4*)(Wb + (size_t)r0 * ldw + kt + kq);
        float4 b1 = *(const float4*)(Wb + (size_t)(r0 + 64) * ldw + kt + kq);
        As[kq + 0][r0] = a0.x; As[kq + 1][r0] = a0.y; As[kq + 2][r0] = a0.z; As[kq + 3][r0] = a0.w;
        As[kq + 0][r0 + 64] = a1.x; As[kq + 1][r0 + 64] = a1.y; As[kq + 2][r0 + 64] = a1.z; As[kq + 3][r0 + 64] = a1.w;
        Bs[kq + 0][r0] = b0.x; Bs[kq + 1][r0] = b0.y; Bs[kq + 2][r0] = b0.z; Bs[kq + 3][r0] = b0.w;
        Bs[kq + 0][r0 + 64] = b1.x; Bs[kq + 1][r0 + 64] = b1.y; Bs[kq + 2][r0 + 64] = b1.z; Bs[kq + 3][r0 + 64] = b1.w;
        __syncthreads();
#pragma unroll
        for (int k = 0; k < 16; k++) {
            float av[8], bv[8];
            *(float4*)(av)     = *(const float4*)&As[k][ty * 4];
            *(float4*)(av + 4) = *(const float4*)&As[k][64 + ty * 4];
            *(float4*)(bv)     = *(const float4*)&Bs[k][tx * 4];
            *(float4*)(bv + 4) = *(const float4*)&Bs[k][64 + tx * 4];
#pragma unroll
            for (int i = 0; i < 8; i++)
#pragma unroll
                for (int j = 0; j < 8; j++) acc[i][j] += av[i] * bv[j];
        }
        __syncthreads();
    }

#pragma unroll
    for (int i = 0; i < 8; i++) {
        int row = blockIdx.y * 128 + ((i < 4) ? (ty * 4 + i) : (64 + ty * 4 + (i - 4)));
#pragma unroll
        for (int jh = 0; jh < 2; jh++) {
            int col = blockIdx.x * 128 + ((jh == 0) ? (tx * 4) : (64 + tx * 4));
            float4 o;
            float bx = 0.f, by = 0.f, bz = 0.f, bw = 0.f;
            if (bias) {
                float4 bb = *(const float4*)(bias + col);
                bx = bb.x; by = bb.y; bz = bb.z; bw = bb.w;
            }
            o.x = acc[i][jh * 4 + 0] + bx;
            o.y = acc[i][jh * 4 + 1] + by;
            o.z = acc[i][jh * 4 + 2] + bz;
            o.w = acc[i][jh * 4 + 3] + bw;
            *(float4*)(C + (size_t)row * ldc + col) = o;
        }
    }
}

// ---------------- small kernels ----------------
__global__ void zero_f(float* p, int n)
{
    int i = blockIdx.x * blockDim.x + threadIdx.x;
    if (i < n) p[i] = 0.f;
}

__global__ void build_nwc(const float* __restrict__ wc, float* __restrict__ nwc)
{
    __shared__ float red[1024];
    int t = threadIdx.x;
    float w = wc[t] * (t == BOUND ? 0.1f : 1.0f);
    red[t] = w;
    __syncthreads();
    for (int off = 512; off; off >>= 1) {
        if (t < off) red[t] += red[t + off];
        __syncthreads();
    }
    float denom = red[0];
    nwc[t] = (denom > 0.f) ? (w / denom) : w;
}

__global__ void build_wc(const float* __restrict__ Wih, const float* __restrict__ Whh,
                         const float* __restrict__ bih, const float* __restrict__ bhh,
                         float* __restrict__ Wc, float* __restrict__ bc)
{
    int idx = blockIdx.x * blockDim.x + threadIdx.x;
    if (idx < G4H * KC) {
        int n = idx / KC, k = idx % KC;
        Wc[idx] = (k < E) ? Wih[n * E + k] : Whh[n * H + (k - E)];
    }
    if (idx < G4H) bc[idx] = bih[idx] + bhh[idx];
}

__global__ void init_sender(int* tok, int* sl, float* vl, int* m)
{
    int b = blockIdx.x * blockDim.x + threadIdx.x;
    if (b < B) {
        tok[b] = BOUND;
        sl[b] = LP1;
        vl[b] = 0.f;
        m[b * LP1] = BOUND;
    }
}

// xh[b, 0:E] = emb[toks[b*tstride+toff]]
__global__ void gather_rows(const float* __restrict__ emb, const int* __restrict__ toks,
                            int tstride, int toff, float* __restrict__ xh)
{
    int idx = blockIdx.x * blockDim.x + threadIdx.x;
    if (idx >= B * (E / 4)) return;
    int b = idx >> 7;       // E/4 = 128
    int e4 = idx & 127;
    int tk = __ldg(&toks[b * tstride + toff]);
    ((float4*)(xh + (size_t)b * KC))[e4] = ((const float4*)(emb + (size_t)tk * E))[e4];
}

__global__ void zero_hpart(float* __restrict__ xh)
{
    int idx = blockIdx.x * blockDim.x + threadIdx.x;
    if (idx >= B * H) return;
    int b = idx >> 10, j = idx & 1023;
    xh[(size_t)b * KC + E + j] = 0.f;
}

__global__ void lstm_gate(const float* __restrict__ g, float* __restrict__ c, float* __restrict__ xh)
{
    int idx = blockIdx.x * blockDim.x + threadIdx.x;
    if (idx >= B * H) return;
    int b = idx >> 10, j = idx & 1023;
    const float* gr = g + (size_t)b * G4H;
    float gi = gr[j], gf = gr[j + H], gg = gr[j + 2 * H], go = gr[j + 3 * H];
    float cc = c[idx];
    float si = 1.f / (1.f + expf(-gi));
    float sf = 1.f / (1.f + expf(-gf));
    float so = 1.f / (1.f + expf(-go));
    float nc = sf * cc + si * tanhf(gg);
    c[idx] = nc;
    xh[(size_t)b * KC + E + j] = so * tanhf(nc);
}

// argmax (first-index tie-break) + log_softmax CE on (scores - nwc), seq-length update
__global__ void score_step(const float* __restrict__ scores, const float* __restrict__ nwc,
                           int* tok, int* sl, float* vl, int* m, int step)
{
    __shared__ float sBest[256];
    __shared__ int   sIdx[256];
    __shared__ float sLM[256];
    __shared__ float sSum[256];
    int b = blockIdx.x, tid = threadIdx.x;
    const float* srow = scores + (size_t)b * V;

    float best = -1e30f; int bidx = 0; float lmax = -1e30f;
    for (int v = tid; v < V; v += 256) {
        float s = srow[v];
        if (s > best) { best = s; bidx = v; }
        float lg = s - nwc[v];
        lmax = fmaxf(lmax, lg);
    }
    sBest[tid] = best; sIdx[tid] = bidx; sLM[tid] = lmax;
    __syncthreads();
    for (int off = 128; off; off >>= 1) {
        if (tid < off) {
            float ob = sBest[tid + off]; int oi = sIdx[tid + off];
            if (ob > sBest[tid] || (ob == sBest[tid] && oi < sIdx[tid])) { sBest[tid] = ob; sIdx[tid] = oi; }
            sLM[tid] = fmaxf(sLM[tid], sLM[tid + off]);
        }
        __syncthreads();
    }
    float LM = sLM[0];
    int t = sIdx[0];
    __syncthreads();

    float ssum = 0.f;
    for (int v = tid; v < V; v += 256) ssum += expf(srow[v] - nwc[v] - LM);
    sSum[tid] = ssum;
    __syncthreads();
    for (int off = 128; off; off >>= 1) {
        if (tid < off) sSum[tid] += sSum[tid + off];
        __syncthreads();
    }
    if (tid == 0) {
        float ce = logf(sSum[0]) + LM - (srow[t] - nwc[t]);
        vl[b] += ce;
        tok[b] = t;
        if (t == BOUND && sl[b] == LP1) sl[b] = step + 2;
        m[b * LP1 + step + 1] = t;
    }
}

__global__ void pad_m(int* __restrict__ m, const int* __restrict__ sl)
{
    int idx = blockIdx.x * blockDim.x + threadIdx.x;
    if (idx >= B * LP1) return;
    int b = idx / LP1, pos = idx % LP1;
    if (pos >= sl[b]) m[idx] = BOUND;
}

__global__ void hist_m(const int* __restrict__ m, float* __restrict__ wcnt)
{
    int idx = blockIdx.x * blockDim.x + threadIdx.x;
    if (idx < B * LP1) atomicAdd(&wcnt[m[idx]], 1.0f);
}

__global__ void hinge_kernel(const float* __restrict__ target, const float* __restrict__ dis,
                             const float* __restrict__ r, const float* __restrict__ vl,
                             float* __restrict__ loss, float* __restrict__ acc)
{
    __shared__ float red[4][257];
    int b = blockIdx.x, t = threadIdx.x;
    const float* rr = r + (size_t)b * F;
    const float* tg = target + (size_t)b * F;
    float s0 = 0.f, s1 = 0.f, s2 = 0.f, s3 = 0.f;
    for (int f = t; f < F; f += 256) {
        float rv = rr[f];
        s0 += tg[f] * rv;
        s1 += dis[(size_t)0 * B * F + (size_t)b * F + f] * rv;
        s2 += dis[(size_t)1 * B * F + (size_t)b * F + f] * rv;
        s3 += dis[(size_t)2 * B * F + (size_t)b * F + f] * rv;
    }
    red[0][t] = s0; red[1][t] = s1; red[2][t] = s2; red[3][t] = s3;
    __syncthreads();
    for (int off = 128; off; off >>= 1) {
        if (t < off) {
#pragma unroll
            for (int q = 0; q < 4; q++) red[q][t] += red[q][t + off];
        }
        __syncthreads();
    }
    if (t == 0) {
        float ts = red[0][0], d0 = red[1][0], d1 = red[2][0], d2 = red[3][0];
        float lo = fmaxf(0.f, 1.f - ts + d0) + fmaxf(0.f, 1.f - ts + d1) + fmaxf(0.f, 1.f - ts + d2);
        loss[b] = lo + 0.1f * vl[b];
        acc[b] = (ts >= d0 && ts >= d1 && ts >= d2) ? 1.f : 0.f;
    }
}

__global__ void finalize(const float* __restrict__ loss, const float* __restrict__ acc, float* __restrict__ out)
{
    __shared__ float rl[1024], ra[1024];
    int t = threadIdx.x;
    float s = 0.f, a = 0.f;
    for (int i = t; i < B; i += 1024) { s += loss[i]; a += acc[i]; }
    rl[t] = s; ra[t] = a;
    __syncthreads();
    for (int off = 512; off; off >>= 1) {
        if (t < off) { rl[t] += rl[t + off]; ra[t] += ra[t + off]; }
        __syncthreads();
    }
    if (t == 0) { out[0] = rl[0] / (float)B; out[1] = ra[0] / (float)B; }
}

__global__ void write_m(const int* __restrict__ m, float* __restrict__ out)
{
    int idx = blockIdx.x * blockDim.x + threadIdx.x;
    if (idx < B * LP1) out[2 + idx] = (float)m[idx];
}

__global__ void write_wc(const float* __restrict__ wcnt, float* __restrict__ out)
{
    int v = blockIdx.x * blockDim.x + threadIdx.x;
    if (v < V) out[2 + B * LP1 + v] = wcnt[v];
}

// ---------------- launch ----------------
extern "C" void kernel_launch(void* const* d_in, const int* in_sizes, int n_in,
                              void* d_out, int out_size)
{
    const float* target = (const float*)d_in[0];
    const float* dis    = (const float*)d_in[1];
    const float* wcin   = (const float*)d_in[2];
    const float* emb_s  = (const float*)d_in[3];
    const float* affsW  = (const float*)d_in[4];
    const float* affsb  = (const float*)d_in[5];
    const float* Wih    = (const float*)d_in[6];
    const float* Whh    = (const float*)d_in[7];
    const float* bih    = (const float*)d_in[8];
    const float* bhh    = (const float*)d_in[9];
    const float* lpW    = (const float*)d_in[10];
    const float* lpb    = (const float*)d_in[11];
    const float* emb_r  = (const float*)d_in[12];
    const float* rWih   = (const float*)d_in[13];
    const float* rWhh   = (const float*)d_in[14];
    const float* rbih   = (const float*)d_in[15];
    const float* rbhh   = (const float*)d_in[16];
    const float* affrW  = (const float*)d_in[17];
    const float* affrb  = (const float*)d_in[18];
    float* out = (float*)d_out;

    float *p_c, *p_xh, *p_gates, *p_scores, *p_vl, *p_Wc, *p_bc, *p_WcR, *p_bcR;
    float *p_nwc, *p_r, *p_loss, *p_acc, *p_wcnt;
    int *p_tok, *p_sl, *p_m;
    cudaGetSymbolAddress((void**)&p_c, g_c);
    cudaGetSymbolAddress((void**)&p_xh, g_xh);
    cudaGetSymbolAddress((void**)&p_gates, g_gates);
    cudaGetSymbolAddress((void**)&p_scores, g_scores);
    cudaGetSymbolAddress((void**)&p_vl, g_vl);
    cudaGetSymbolAddress((void**)&p_Wc, g_Wc);
    cudaGetSymbolAddress((void**)&p_bc, g_bc);
    cudaGetSymbolAddress((void**)&p_WcR, g_WcR);
    cudaGetSymbolAddress((void**)&p_bcR, g_bcR);
    cudaGetSymbolAddress((void**)&p_nwc, g_nwc);
    cudaGetSymbolAddress((void**)&p_r, g_r);
    cudaGetSymbolAddress((void**)&p_loss, g_loss);
    cudaGetSymbolAddress((void**)&p_acc, g_acc);
    cudaGetSymbolAddress((void**)&p_wcnt, g_wcnt);
    cudaGetSymbolAddress((void**)&p_tok, g_tok);
    cudaGetSymbolAddress((void**)&p_sl, g_sl);
    cudaGetSymbolAddress((void**)&p_m, g_m);

    const int BH = B * H;

    // setup
    build_nwc<<<1, 1024>>>(wcin, p_nwc);
    build_wc<<<(G4H * KC + 255) / 256, 256>>>(Wih, Whh, bih, bhh, p_Wc, p_bc);
    build_wc<<<(G4H * KC + 255) / 256, 256>>>(rWih, rWhh, rbih, rbhh, p_WcR, p_bcR);
    zero_f<<<(BH + 255) / 256, 256>>>(p_c, BH);
    init_sender<<<(B + 255) / 256, 256>>>(p_tok, p_sl, p_vl, p_m);

    // h0 = target @ aff_s_W^T + aff_s_b  -> xh h-part
    sgemm_tn<<<dim3(H / 128, B / 128), 256>>>(target, F, affsW, F, p_xh + E, KC, affsb, F);

    // sender loop
    for (int i = 0; i < L; i++) {
        gather_rows<<<(B * (E / 4) + 255) / 256, 256>>>(emb_s, p_tok, 1, 0, p_xh);
        sgemm_tn<<<dim3(G4H / 128, B / 128), 256>>>(p_xh, KC, p_Wc, KC, p_gates, G4H, p_bc, KC);
        lstm_gate<<<(BH + 255) / 256, 256>>>(p_gates, p_c, p_xh);
        sgemm_tn<<<dim3(V / 128, B / 128), 256>>>(p_xh + E, KC, lpW, H, p_scores, V, lpb, H);
        score_step<<<B, 256>>>(p_scores, p_nwc, p_tok, p_sl, p_vl, p_m, i);
    }

    pad_m<<<(B * LP1 + 255) / 256, 256>>>(p_m, p_sl);
    zero_f<<<(V + 255) / 256, 256>>>(p_wcnt, V);
    hist_m<<<(B * LP1 + 255) / 256, 256>>>(p_m, p_wcnt);

    // receiver
    zero_f<<<(BH + 255) / 256, 256>>>(p_c, BH);
    zero_hpart<<<(BH + 255) / 256, 256>>>(p_xh);
    for (int t = 0; t < LP1; t++) {
        gather_rows<<<(B * (E / 4) + 255) / 256, 256>>>(emb_r, p_m, LP1, t, p_xh);
        sgemm_tn<<<dim3(G4H / 128, B / 128), 256>>>(p_xh, KC, p_WcR, KC, p_gates, G4H, p_bcR, KC);
        lstm_gate<<<(BH + 255) / 256, 256>>>(p_gates, p_c, p_xh);
    }

    // r = hr @ aff_r_W^T + aff_r_b
    sgemm_tn<<<dim3(F / 128, B / 128), 256>>>(p_xh + E, KC, affrW, H, p_r, F, affrb, H);

    hinge_kernel<<<B, 256>>>(target, dis, p_r, p_vl, p_loss, p_acc);
    finalize<<<1, 1024>>>(p_loss, p_acc, out);
    write_m<<<(B * LP1 + 255) / 256, 256>>>(p_m, out);
    write_wc<<<(V + 255) / 256, 256>>>(p_wcnt, out);
}

// round 5
// speedup vs baseline: 1.8505x; 1.8505x over previous
#include <cuda_runtime.h>
#include <cuda_fp16.h>
#include <math.h>
#include <stdint.h>

// Problem dims
#define B     4096
#define F     4096
#define V     1024
#define E     512
#define H     1024
#define L     30
#define G4H   4096
#define KC    1536
#define BOUND 1023
#define LP1   31

// ================= PTX helpers (compute_103-base legal) =================
#define CP_ASYNC16(dst, src) asm volatile("cp.async.cg.shared.global [%0], [%1], 16;" :: "r"(dst), "l"(src))
#define CP_COMMIT()          asm volatile("cp.async.commit_group;" ::: "memory")
#define CP_WAIT0()           asm volatile("cp.async.wait_group 0;" ::: "memory")
#define LDMX4(r0,r1,r2,r3, addr) \
    asm volatile("ldmatrix.sync.aligned.m8n8.x4.shared.b16 {%0,%1,%2,%3}, [%4];" \
        : "=r"(r0), "=r"(r1), "=r"(r2), "=r"(r3) : "r"(addr))

__device__ __forceinline__ void mma16816(float* d, const uint32_t* a, uint32_t b0, uint32_t b1)
{
    asm volatile(
        "mma.sync.aligned.m16n8k16.row.col.f32.f16.f16.f32 "
        "{%0,%1,%2,%3}, {%4,%5,%6,%7}, {%8,%9}, {%0,%1,%2,%3};"
        : "+f"(d[0]), "+f"(d[1]), "+f"(d[2]), "+f"(d[3])
        : "r"(a[0]), "r"(a[1]), "r"(a[2]), "r"(a[3]), "r"(b0), "r"(b1));
}

// ================= device scratch =================
__device__ float g_c[B * H];
__device__ float g_gates[B * G4H];
__device__ float g_scores[B * V];
__device__ int   g_tok[B];
__device__ int   g_sl[B];
__device__ float g_vl[B];
__device__ int   g_m[B * LP1];
__device__ float g_nwc[V];
__device__ float g_r[B * F];
__device__ float g_loss[B];
__device__ float g_acc[B];
__device__ float g_wcnt[V];
__device__ float g_bc[G4H];
__device__ float g_bcR[G4H];

// fp16 split-2 planes (plane1 pre-scaled by 2048)
__device__ __half g_h0p[B * H],  g_h1p[B * H];        // hidden state planes
__device__ __half g_W0p[G4H * KC], g_W1p[G4H * KC];   // sender concat weights
__device__ __half g_R0p[G4H * KC], g_R1p[G4H * KC];   // receiver concat weights
__device__ __half g_L0p[V * H],  g_L1p[V * H];        // lp_W
__device__ __half g_S0p[H * F],  g_S1p[H * F];        // aff_s_W
__device__ __half g_A0p[F * H],  g_A1p[F * H];        // aff_r_W
__device__ __half g_T0p[B * F],  g_T1p[B * F];        // target
__device__ __half g_E0p[V * E],  g_E1p[V * E];        // emb_s
__device__ __half g_F0p[V * E],  g_F1p[V * E];        // emb_r

// ================= HMMA GEMM =================
// C[M,N] = A*W^T + bias, fp32-accurate split-2 fp16 (3 passes).
// A source: hp planes rows (k >= gatherK) + token-gathered emb planes (k < gatherK).
// Tile: 128x128x32, 256 threads, warp tile 32x64.
// SMPAD = 40 halves -> 80-byte row stride: 16B-aligned (cp.async/ldmatrix legal)
// and conflict-free for ldmatrix (8 rows @80B hit 8 distinct 16B slots mod 128B).
#define SMPAD 40

__global__ void __launch_bounds__(256)
hmma_gemm(const __half* __restrict__ A0, const __half* __restrict__ A1, int lda,
          const __half* __restrict__ EA0, const __half* __restrict__ EA1, int lde,
          const int* __restrict__ toks, int tok_stride, int gatherK,
          const __half* __restrict__ B0, const __half* __restrict__ B1, int ldb,
          float* __restrict__ C, int ldc, const float* __restrict__ bias, int K)
{
    __shared__ __half As[2][128 * SMPAD];
    __shared__ __half Bs[2][128 * SMPAD];
    __shared__ int stok[128];

    const int tid = threadIdx.x;
    const int m0 = blockIdx.y * 128, n0 = blockIdx.x * 128;
    if (toks != nullptr && tid < 128) stok[tid] = toks[(size_t)(m0 + tid) * tok_stride];
    __syncthreads();

    const int wid = tid >> 5, lane = tid & 31;
    const int wm = wid & 3, wn = wid >> 2;     // warp tile: rows wm*32, cols wn*64
    const uint32_t sA = (uint32_t)__cvta_generic_to_shared(&As[0][0]);
    const uint32_t sB = (uint32_t)__cvta_generic_to_shared(&Bs[0][0]);
    const uint32_t bufStride = 128 * SMPAD * 2;   // bytes

    float acc[2][8][4];
#pragma unroll
    for (int mt = 0; mt < 2; mt++)
#pragma unroll
        for (int nt = 0; nt < 8; nt++)
#pragma unroll
            for (int q = 0; q < 4; q++) acc[mt][nt][q] = 0.f;

    const int KT = K >> 5;

    // pass p: 0:(A0,B1s) 1:(A1s,B0) 2:(A0,B0); scale acc by 2^-11 after pass 1
#pragma unroll 1
    for (int pass = 0; pass < 3; pass++) {
        const __half* pA = (pass == 1) ? A1 : A0;
        const __half* pE = (pass == 1) ? EA1 : EA0;
        const __half* pB = (pass == 0) ? B1 : B0;
        __syncthreads();

        // prologue: load tile 0 into buf 0
        {
            const int k0 = 0;
#pragma unroll
            for (int i = 0; i < 2; i++) {
                int id = tid + i * 256;
                int r = id >> 2, c = id & 3;
                const __half* src;
                if (gatherK && k0 < gatherK)
                    src = pE + (size_t)stok[r] * lde + k0 + c * 8;
                else
                    src = pA + (size_t)(m0 + r) * lda + (k0 - gatherK) + c * 8;
                CP_ASYNC16(sA + (uint32_t)((r * SMPAD + c * 8) * 2), src);
                const __half* srcb = pB + (size_t)(n0 + r) * ldb + k0 + c * 8;
                CP_ASYNC16(sB + (uint32_t)((r * SMPAD + c * 8) * 2), srcb);
            }
            CP_COMMIT();
        }

        for (int kt = 0; kt < KT; kt++) {
            const int cur = kt & 1;
            CP_WAIT0();
            __syncthreads();
            if (kt + 1 < KT) {
                const int k0 = (kt + 1) << 5;
                const int nb = cur ^ 1;
#pragma unroll
                for (int i = 0; i < 2; i++) {
                    int id = tid + i * 256;
                    int r = id >> 2, c = id & 3;
                    const __half* src;
                    if (gatherK && k0 < gatherK)
                        src = pE + (size_t)stok[r] * lde + k0 + c * 8;
                    else
                        src = pA + (size_t)(m0 + r) * lda + (k0 - gatherK) + c * 8;
                    CP_ASYNC16(sA + (uint32_t)(nb * bufStride + (r * SMPAD + c * 8) * 2), src);
                    const __half* srcb = pB + (size_t)(n0 + r) * ldb + k0 + c * 8;
                    CP_ASYNC16(sB + (uint32_t)(nb * bufStride + (r * SMPAD + c * 8) * 2), srcb);
                }
                CP_COMMIT();
            }
            // compute on buffer cur
            const uint32_t baseA = sA + cur * bufStride;
            const uint32_t baseB = sB + cur * bufStride;
#pragma unroll
            for (int kh = 0; kh < 2; kh++) {
                const int colh = kh * 16 + ((lane >> 4) & 1) * 8;
                uint32_t a[2][4];
#pragma unroll
                for (int mt = 0; mt < 2; mt++) {
                    int row = wm * 32 + mt * 16 + (lane & 15);
                    uint32_t addr = baseA + (uint32_t)((row * SMPAD + colh) * 2);
                    LDMX4(a[mt][0], a[mt][1], a[mt][2], a[mt][3], addr);
                }
                uint32_t b[4][4];
#pragma unroll
                for (int bt = 0; bt < 4; bt++) {
                    int row = wn * 64 + bt * 16 + (lane & 15);
                    uint32_t addr = baseB + (uint32_t)((row * SMPAD + colh) * 2);
                    LDMX4(b[bt][0], b[bt][1], b[bt][2], b[bt][3], addr);
                }
#pragma unroll
                for (int mt = 0; mt < 2; mt++)
#pragma unroll
                    for (int nt = 0; nt < 8; nt++) {
                        int bt = nt >> 1, hi = nt & 1;
                        mma16816(acc[mt][nt], a[mt], b[bt][hi], b[bt][2 + hi]);
                    }
            }
            __syncthreads();
        }

        if (pass == 1) {
            const float s = 1.f / 2048.f;
#pragma unroll
            for (int mt = 0; mt < 2; mt++)
#pragma unroll
                for (int nt = 0; nt < 8; nt++)
#pragma unroll
                    for (int q = 0; q < 4; q++) acc[mt][nt][q] *= s;
        }
    }

    // epilogue
    const int g = lane >> 2, q2 = (lane & 3) * 2;
#pragma unroll
    for (int mt = 0; mt < 2; mt++) {
        int row = m0 + wm * 32 + mt * 16 + g;
#pragma unroll
        for (int nt = 0; nt < 8; nt++) {
            int col = n0 + wn * 64 + nt * 8 + q2;
            float2 bb = *(const float2*)(bias + col);
            float2 o0 = { acc[mt][nt][0] + bb.x, acc[mt][nt][1] + bb.y };
            float2 o1 = { acc[mt][nt][2] + bb.x, acc[mt][nt][3] + bb.y };
            *(float2*)(C + (size_t)row * ldc + col) = o0;
            *(float2*)(C + (size_t)(row + 8) * ldc + col) = o1;
        }
    }
}

// ================= split / elementwise kernels =================
__device__ __forceinline__ void split2h(float x, __half& o0, __half& o1)
{
    __half h0 = __float2half_rn(x);
    float r = (x - __half2float(h0)) * 2048.f;
    o0 = h0;
    o1 = __float2half_rn(r);
}

__global__ void split2_kernel(const float* __restrict__ src, int n,
                              __half* __restrict__ p0, __half* __restrict__ p1)
{
    int i = blockIdx.x * blockDim.x + threadIdx.x;
    if (i < n) split2h(src[i], p0[i], p1[i]);
}

__global__ void build_wc_split2(const float* __restrict__ Wih, const float* __restrict__ Whh,
                                __half* __restrict__ p0, __half* __restrict__ p1)
{
    int idx = blockIdx.x * blockDim.x + threadIdx.x;
    if (idx >= G4H * KC) return;
    int n = idx / KC, k = idx % KC;
    float w = (k < E) ? Wih[n * E + k] : Whh[n * H + (k - E)];
    split2h(w, p0[idx], p1[idx]);
}

__global__ void bias_comb(const float* __restrict__ bih, const float* __restrict__ bhh,
                          float* __restrict__ bc)
{
    int i = blockIdx.x * blockDim.x + threadIdx.x;
    if (i < G4H) bc[i] = bih[i] + bhh[i];
}

__global__ void zero_f(float* p, int n)
{
    int i = blockIdx.x * blockDim.x + threadIdx.x;
    if (i < n) p[i] = 0.f;
}

__global__ void zero_h2(__half* p0, __half* p1, int n)
{
    int i = blockIdx.x * blockDim.x + threadIdx.x;
    if (i < n) { p0[i] = __float2half(0.f); p1[i] = __float2half(0.f); }
}

__global__ void build_nwc(const float* __restrict__ wc, float* __restrict__ nwc)
{
    __shared__ float red[1024];
    int t = threadIdx.x;
    float w = wc[t] * (t == BOUND ? 0.1f : 1.0f);
    red[t] = w;
    __syncthreads();
    for (int off = 512; off; off >>= 1) {
        if (t < off) red[t] += red[t + off];
        __syncthreads();
    }
    float denom = red[0];
    nwc[t] = (denom > 0.f) ? (w / denom) : w;
}

__global__ void init_sender(int* tok, int* sl, float* vl, int* m)
{
    int b = blockIdx.x * blockDim.x + threadIdx.x;
    if (b < B) {
        tok[b] = BOUND;
        sl[b] = LP1;
        vl[b] = 0.f;
        m[b * LP1] = BOUND;
    }
}

__global__ void lstm_gate_split2(const float* __restrict__ g, float* __restrict__ c,
                                 __half* __restrict__ h0p, __half* __restrict__ h1p)
{
    int idx = blockIdx.x * blockDim.x + threadIdx.x;
    if (idx >= B * H) return;
    int b = idx >> 10, j = idx & 1023;
    const float* gr = g + (size_t)b * G4H;
    float gi = gr[j], gf = gr[j + H], gg = gr[j + 2 * H], go = gr[j + 3 * H];
    float cc = c[idx];
    float si = 1.f / (1.f + expf(-gi));
    float sf = 1.f / (1.f + expf(-gf));
    float so = 1.f / (1.f + expf(-go));
    float nc = sf * cc + si * tanhf(gg);
    c[idx] = nc;
    float h = so * tanhf(nc);
    split2h(h, h0p[idx], h1p[idx]);
}

__global__ void h_split2(const float* __restrict__ hsrc,
                         __half* __restrict__ h0p, __half* __restrict__ h1p)
{
    int idx = blockIdx.x * blockDim.x + threadIdx.x;
    if (idx >= B * H) return;
    split2h(hsrc[idx], h0p[idx], h1p[idx]);
}

__global__ void score_step(const float* __restrict__ scores, const float* __restrict__ nwc,
                           int* tok, int* sl, float* vl, int* m, int step)
{
    __shared__ float sBest[256];
    __shared__ int   sIdx[256];
    __shared__ float sLM[256];
    __shared__ float sSum[256];
    int b = blockIdx.x, tid = threadIdx.x;
    const float* srow = scores + (size_t)b * V;

    float best = -1e30f; int bidx = 0; float lmax = -1e30f;
    for (int v = tid; v < V; v += 256) {
        float s = srow[v];
        if (s > best) { best = s; bidx = v; }
        float lg = s - nwc[v];
        lmax = fmaxf(lmax, lg);
    }
    sBest[tid] = best; sIdx[tid] = bidx; sLM[tid] = lmax;
    __syncthreads();
    for (int off = 128; off; off >>= 1) {
        if (tid < off) {
            float ob = sBest[tid + off]; int oi = sIdx[tid + off];
            if (ob > sBest[tid] || (ob == sBest[tid] && oi < sIdx[tid])) { sBest[tid] = ob; sIdx[tid] = oi; }
            sLM[tid] = fmaxf(sLM[tid], sLM[tid + off]);
        }
        __syncthreads();
    }
    float LM = sLM[0];
    int t = sIdx[0];
    __syncthreads();

    float ssum = 0.f;
    for (int v = tid; v < V; v += 256) ssum += expf(srow[v] - nwc[v] - LM);
    sSum[tid] = ssum;
    __syncthreads();
    for (int off = 128; off; off >>= 1) {
        if (tid < off) sSum[tid] += sSum[tid + off];
        __syncthreads();
    }
    if (tid == 0) {
        float ce = logf(sSum[0]) + LM - (srow[t] - nwc[t]);
        vl[b] += ce;
        tok[b] = t;
        if (t == BOUND && sl[b] == LP1) sl[b] = step + 2;
        m[b * LP1 + step + 1] = t;
    }
}

__global__ void pad_m(int* __restrict__ m, const int* __restrict__ sl)
{
    int idx = blockIdx.x * blockDim.x + threadIdx.x;
    if (idx >= B * LP1) return;
    int b = idx / LP1, pos = idx % LP1;
    if (pos >= sl[b]) m[idx] = BOUND;
}

__global__ void hist_m(const int* __restrict__ m, float* __restrict__ wcnt)
{
    int idx = blockIdx.x * blockDim.x + threadIdx.x;
    if (idx < B * LP1) atomicAdd(&wcnt[m[idx]], 1.0f);
}

__global__ void hinge_kernel(const float* __restrict__ target, const float* __restrict__ dis,
                             const float* __restrict__ r, const float* __restrict__ vl,
                             float* __restrict__ loss, float* __restrict__ acc)
{
    __shared__ float red[4][257];
    int b = blockIdx.x, t = threadIdx.x;
    const float* rr = r + (size_t)b * F;
    const float* tg = target + (size_t)b * F;
    float s0 = 0.f, s1 = 0.f, s2 = 0.f, s3 = 0.f;
    for (int f = t; f < F; f += 256) {
        float rv = rr[f];
        s0 += tg[f] * rv;
        s1 += dis[(size_t)0 * B * F + (size_t)b * F + f] * rv;
        s2 += dis[(size_t)1 * B * F + (size_t)b * F + f] * rv;
        s3 += dis[(size_t)2 * B * F + (size_t)b * F + f] * rv;
    }
    red[0][t] = s0; red[1][t] = s1; red[2][t] = s2; red[3][t] = s3;
    __syncthreads();
    for (int off = 128; off; off >>= 1) {
        if (t < off) {
#pragma unroll
            for (int q = 0; q < 4; q++) red[q][t] += red[q][t + off];
        }
        __syncthreads();
    }
    if (t == 0) {
        float ts = red[0][0], d0 = red[1][0], d1 = red[2][0], d2 = red[3][0];
        float lo = fmaxf(0.f, 1.f - ts + d0) + fmaxf(0.f, 1.f - ts + d1) + fmaxf(0.f, 1.f - ts + d2);
        loss[b] = lo + 0.1f * vl[b];
        acc[b] = (ts >= d0 && ts >= d1 && ts >= d2) ? 1.f : 0.f;
    }
}

__global__ void finalize(const float* __restrict__ loss, const float* __restrict__ acc, float* __restrict__ out)
{
    __shared__ float rl[1024], ra[1024];
    int t = threadIdx.x;
    float s = 0.f, a = 0.f;
    for (int i = t; i < B; i += 1024) { s += loss[i]; a += acc[i]; }
    rl[t] = s; ra[t] = a;
    __syncthreads();
    for (int off = 512; off; off >>= 1) {
        if (t < off) { rl[t] += rl[t + off]; ra[t] += ra[t + off]; }
        __syncthreads();
    }
    if (t == 0) { out[0] = rl[0] / (float)B; out[1] = ra[0] / (float)B; }
}

__global__ void write_m(const int* __restrict__ m, float* __restrict__ out)
{
    int idx = blockIdx.x * blockDim.x + threadIdx.x;
    if (idx < B * LP1) out[2 + idx] = (float)m[idx];
}

__global__ void write_wc(const float* __restrict__ wcnt, float* __restrict__ out)
{
    int v = blockIdx.x * blockDim.x + threadIdx.x;
    if (v < V) out[2 + B * LP1 + v] = wcnt[v];
}

// ================= launch =================
extern "C" void kernel_launch(void* const* d_in, const int* in_sizes, int n_in,
                              void* d_out, int out_size)
{
    const float* target = (const float*)d_in[0];
    const float* dis    = (const float*)d_in[1];
    const float* wcin   = (const float*)d_in[2];
    const float* emb_s  = (const float*)d_in[3];
    const float* affsW  = (const float*)d_in[4];
    const float* affsb  = (const float*)d_in[5];
    const float* Wih    = (const float*)d_in[6];
    const float* Whh    = (const float*)d_in[7];
    const float* bih    = (const float*)d_in[8];
    const float* bhh    = (const float*)d_in[9];
    const float* lpW    = (const float*)d_in[10];
    const float* lpb    = (const float*)d_in[11];
    const float* emb_r  = (const float*)d_in[12];
    const float* rWih   = (const float*)d_in[13];
    const float* rWhh   = (const float*)d_in[14];
    const float* rbih   = (const float*)d_in[15];
    const float* rbhh   = (const float*)d_in[16];
    const float* affrW  = (const float*)d_in[17];
    const float* affrb  = (const float*)d_in[18];
    float* out = (float*)d_out;

    float *p_c, *p_gates, *p_scores, *p_vl, *p_nwc, *p_r, *p_loss, *p_acc, *p_wcnt, *p_bc, *p_bcR;
    int *p_tok, *p_sl, *p_m;
    __half *h0p, *h1p, *W0p, *W1p, *R0p, *R1p, *L0p, *L1p, *S0p, *S1p, *A0p, *A1p;
    __half *T0p, *T1p, *E0p, *E1p, *Fe0p, *Fe1p;
    cudaGetSymbolAddress((void**)&p_c, g_c);
    cudaGetSymbolAddress((void**)&p_gates, g_gates);
    cudaGetSymbolAddress((void**)&p_scores, g_scores);
    cudaGetSymbolAddress((void**)&p_vl, g_vl);
    cudaGetSymbolAddress((void**)&p_nwc, g_nwc);
    cudaGetSymbolAddress((void**)&p_r, g_r);
    cudaGetSymbolAddress((void**)&p_loss, g_loss);
    cudaGetSymbolAddress((void**)&p_acc, g_acc);
    cudaGetSymbolAddress((void**)&p_wcnt, g_wcnt);
    cudaGetSymbolAddress((void**)&p_bc, g_bc);
    cudaGetSymbolAddress((void**)&p_bcR, g_bcR);
    cudaGetSymbolAddress((void**)&p_tok, g_tok);
    cudaGetSymbolAddress((void**)&p_sl, g_sl);
    cudaGetSymbolAddress((void**)&p_m, g_m);
    cudaGetSymbolAddress((void**)&h0p, g_h0p);  cudaGetSymbolAddress((void**)&h1p, g_h1p);
    cudaGetSymbolAddress((void**)&W0p, g_W0p);  cudaGetSymbolAddress((void**)&W1p, g_W1p);
    cudaGetSymbolAddress((void**)&R0p, g_R0p);  cudaGetSymbolAddress((void**)&R1p, g_R1p);
    cudaGetSymbolAddress((void**)&L0p, g_L0p);  cudaGetSymbolAddress((void**)&L1p, g_L1p);
    cudaGetSymbolAddress((void**)&S0p, g_S0p);  cudaGetSymbolAddress((void**)&S1p, g_S1p);
    cudaGetSymbolAddress((void**)&A0p, g_A0p);  cudaGetSymbolAddress((void**)&A1p, g_A1p);
    cudaGetSymbolAddress((void**)&T0p, g_T0p);  cudaGetSymbolAddress((void**)&T1p, g_T1p);
    cudaGetSymbolAddress((void**)&E0p, g_E0p);  cudaGetSymbolAddress((void**)&E1p, g_E1p);
    cudaGetSymbolAddress((void**)&Fe0p, g_F0p); cudaGetSymbolAddress((void**)&Fe1p, g_F1p);

    const int BH = B * H;

    // ---- setup / weight splitting ----
    build_nwc<<<1, 1024>>>(wcin, p_nwc);
    bias_comb<<<(G4H + 255) / 256, 256>>>(bih, bhh, p_bc);
    bias_comb<<<(G4H + 255) / 256, 256>>>(rbih, rbhh, p_bcR);
    build_wc_split2<<<(G4H * KC + 255) / 256, 256>>>(Wih, Whh, W0p, W1p);
    build_wc_split2<<<(G4H * KC + 255) / 256, 256>>>(rWih, rWhh, R0p, R1p);
    split2_kernel<<<(V * H + 255) / 256, 256>>>(lpW, V * H, L0p, L1p);
    split2_kernel<<<(H * F + 255) / 256, 256>>>(affsW, H * F, S0p, S1p);
    split2_kernel<<<(F * H + 255) / 256, 256>>>(affrW, F * H, A0p, A1p);
    split2_kernel<<<(B * F + 255) / 256, 256>>>(target, B * F, T0p, T1p);
    split2_kernel<<<(V * E + 255) / 256, 256>>>(emb_s, V * E, E0p, E1p);
    split2_kernel<<<(V * E + 255) / 256, 256>>>(emb_r, V * E, Fe0p, Fe1p);
    zero_f<<<(BH + 255) / 256, 256>>>(p_c, BH);
    init_sender<<<(B + 255) / 256, 256>>>(p_tok, p_sl, p_vl, p_m);

    // h0 = target @ aff_s_W^T + aff_s_b  (fp32 temp in g_gates, then split)
    hmma_gemm<<<dim3(H / 128, B / 128), 256>>>(T0p, T1p, F, nullptr, nullptr, 0,
                                               nullptr, 0, 0,
                                               S0p, S1p, F, p_gates, H, affsb, F);
    h_split2<<<(BH + 255) / 256, 256>>>(p_gates, h0p, h1p);

    // ---- sender loop ----
    for (int i = 0; i < L; i++) {
        // gates = [emb(tok) | h] @ Wc^T + bc  (gather fused: k<512 token-indexed)
        hmma_gemm<<<dim3(G4H / 128, B / 128), 256>>>(h0p, h1p, H, E0p, E1p, E,
                                                     p_tok, 1, E,
                                                     W0p, W1p, KC, p_gates, G4H, p_bc, KC);
        lstm_gate_split2<<<(BH + 255) / 256, 256>>>(p_gates, p_c, h0p, h1p);
        hmma_gemm<<<dim3(V / 128, B / 128), 256>>>(h0p, h1p, H, nullptr, nullptr, 0,
                                                   nullptr, 0, 0,
                                                   L0p, L1p, H, p_scores, V, lpb, H);
        score_step<<<B, 256>>>(p_scores, p_nwc, p_tok, p_sl, p_vl, p_m, i);
    }

    pad_m<<<(B * LP1 + 255) / 256, 256>>>(p_m, p_sl);
    zero_f<<<(V + 255) / 256, 256>>>(p_wcnt, V);
    hist_m<<<(B * LP1 + 255) / 256, 256>>>(p_m, p_wcnt);

    // ---- receiver ----
    zero_f<<<(BH + 255) / 256, 256>>>(p_c, BH);
    zero_h2<<<(BH + 255) / 256, 256>>>(h0p, h1p, BH);
    for (int t = 0; t < LP1; t++) {
        hmma_gemm<<<dim3(G4H / 128, B / 128), 256>>>(h0p, h1p, H, Fe0p, Fe1p, E,
                                                     p_m + t, LP1, E,
                                                     R0p, R1p, KC, p_gates, G4H, p_bcR, KC);
        lstm_gate_split2<<<(BH + 255) / 256, 256>>>(p_gates, p_c, h0p, h1p);
    }

    // r = hr @ aff_r_W^T + aff_r_b
    hmma_gemm<<<dim3(F / 128, B / 128), 256>>>(h0p, h1p, H, nullptr, nullptr, 0,
                                               nullptr, 0, 0,
                                               A0p, A1p, H, p_r, F, affrb, H);

    hinge_kernel<<<B, 256>>>(target, dis, p_r, p_vl, p_loss, p_acc);
    finalize<<<1, 1024>>>(p_loss, p_acc, out);
    write_m<<<(B * LP1 + 255) / 256, 256>>>(p_m, out);
    write_wc<<<(V + 255) / 256, 256>>>(p_wcnt, out);
}

// round 6
// speedup vs baseline: 2.4803x; 1.3403x over previous
#include <cuda_runtime.h>
#include <cuda_fp16.h>
#include <math.h>
#include <stdint.h>

// Problem dims
#define B     4096
#define F     4096
#define V     1024
#define E     512
#define H     1024
#define L     30
#define G4H   4096
#define KC    1536
#define BOUND 1023
#define LP1   31

// ================= PTX helpers =================
#define CP_ASYNC16(dst, src) asm volatile("cp.async.cg.shared.global [%0], [%1], 16;" :: "r"(dst), "l"(src))
#define CP_COMMIT()          asm volatile("cp.async.commit_group;" ::: "memory")
#define CP_WAIT0()           asm volatile("cp.async.wait_group 0;" ::: "memory")
#define LDMX4(r0,r1,r2,r3, addr) \
    asm volatile("ldmatrix.sync.aligned.m8n8.x4.shared.b16 {%0,%1,%2,%3}, [%4];" \
        : "=r"(r0), "=r"(r1), "=r"(r2), "=r"(r3) : "r"(addr))

__device__ __forceinline__ void mma16816(float* d, const uint32_t* a, uint32_t b0, uint32_t b1)
{
    asm volatile(
        "mma.sync.aligned.m16n8k16.row.col.f32.f16.f16.f32 "
        "{%0,%1,%2,%3}, {%4,%5,%6,%7}, {%8,%9}, {%0,%1,%2,%3};"
        : "+f"(d[0]), "+f"(d[1]), "+f"(d[2]), "+f"(d[3])
        : "r"(a[0]), "r"(a[1]), "r"(a[2]), "r"(a[3]), "r"(b0), "r"(b1));
}

// ================= device scratch =================
__device__ float g_c[B * H];
__device__ float g_gates[B * G4H];
__device__ float g_scores[B * V];
__device__ int   g_tok[B];
__device__ int   g_sl[B];
__device__ float g_vl[B];
__device__ int   g_m[B * LP1];
__device__ float g_nwc[V];
__device__ float g_r[B * F];
__device__ float g_loss[B];
__device__ float g_acc[B];
__device__ float g_wcnt[V];
__device__ float g_bc[G4H];        // interleaved combined bias (sender)
__device__ float g_bcR[G4H];       // interleaved combined bias (receiver)
__device__ float g_Ts[V * G4H];    // emb_s @ Wc^T + bias (interleaved cols)
__device__ float g_Tr[V * G4H];    // emb_r @ Rc^T + bias

// fp16 split-2 planes (plane1 pre-scaled by 2048)
__device__ __half g_h0a[B * H], g_h1a[B * H];          // hidden state planes buf A
__device__ __half g_h0b[B * H], g_h1b[B * H];          // hidden state planes buf B
__device__ __half g_W0p[G4H * KC], g_W1p[G4H * KC];    // sender concat W (interleaved rows)
__device__ __half g_R0p[G4H * KC], g_R1p[G4H * KC];    // receiver concat W (interleaved rows)
__device__ __half g_L0p[V * H],  g_L1p[V * H];         // lp_W
__device__ __half g_S0p[H * F],  g_S1p[H * F];         // aff_s_W
__device__ __half g_A0p[F * H],  g_A1p[F * H];         // aff_r_W
__device__ __half g_T0p[B * F],  g_T1p[B * F];         // target
__device__ __half g_E0p[V * E],  g_E1p[V * E];         // emb_s
__device__ __half g_F0p[V * E],  g_F1p[V * E];         // emb_r

// ================= merged 3-product HMMA GEMM =================
// C[M,N] = A*W^T (+bias)  via split-2 fp16 planes, all 3 products in one K-loop.
// mode 0: plain epilogue (C, bias). mode 1: fused LSTM epilogue
//   (adds Ts[tok[b]] which already includes bias, computes c/h, writes split h planes).
#define SMPAD       40
#define TILE_BYTES  (128 * SMPAD * 2)     // 10240
#define STAGE_BYTES (4 * TILE_BYTES)      // 40960
#define DSM_BYTES   (2 * STAGE_BYTES)     // 81920
#define CS_STRIDE   136

__device__ __forceinline__ void ld_stage(uint32_t sbase, int buf,
    const __half* __restrict__ A0, const __half* __restrict__ A1, int lda, int m0,
    const __half* __restrict__ B0p, const __half* __restrict__ B1p, int ldb, int n0,
    int k0, int tid)
{
    uint32_t dst0 = sbase + buf * STAGE_BYTES;
#pragma unroll
    for (int t = 0; t < 4; t++) {
        const __half* pt = (t == 0) ? A0 : (t == 1) ? A1 : (t == 2) ? B0p : B1p;
        const int ld = (t < 2) ? lda : ldb;
        const int r0g = (t < 2) ? m0 : n0;
#pragma unroll
        for (int i = 0; i < 2; i++) {
            int id = tid + i * 256;
            int r = id >> 2, c = id & 3;
            const __half* src = pt + (size_t)(r0g + r) * ld + k0 + c * 8;
            CP_ASYNC16(dst0 + (uint32_t)(t * TILE_BYTES + (r * SMPAD + c * 8) * 2), src);
        }
    }
}

__device__ __forceinline__ void split2h(float x, __half& o0, __half& o1)
{
    __half h0 = __float2half_rn(x);
    float r = (x - __half2float(h0)) * 2048.f;
    o0 = h0;
    o1 = __float2half_rn(r);
}

__global__ void __launch_bounds__(256, 1)
hmma3(const __half* __restrict__ A0, const __half* __restrict__ A1, int lda,
      const __half* __restrict__ B0p, const __half* __restrict__ B1p, int ldb,
      float* __restrict__ C, int ldc, const float* __restrict__ bias, int K,
      int mode,
      const int* __restrict__ toks, int tok_stride,
      const float* __restrict__ Ts,
      float* __restrict__ cst, __half* __restrict__ ho0, __half* __restrict__ ho1)
{
    extern __shared__ __align__(16) char dsm[];
    __shared__ int stok[128];

    const int tid = threadIdx.x;
    const int m0 = blockIdx.y * 128, n0 = blockIdx.x * 128;
    if (mode == 1 && tid < 128) stok[tid] = toks[(size_t)(m0 + tid) * tok_stride];

    const int wid = tid >> 5, lane = tid & 31;
    const int wm = wid & 3, wn = wid >> 2;
    const uint32_t sbase = (uint32_t)__cvta_generic_to_shared(dsm);

    float accM[2][8][4], accC[2][8][4];
#pragma unroll
    for (int mt = 0; mt < 2; mt++)
#pragma unroll
        for (int nt = 0; nt < 8; nt++)
#pragma unroll
            for (int q = 0; q < 4; q++) { accM[mt][nt][q] = 0.f; accC[mt][nt][q] = 0.f; }

    const int KT = K >> 5;

    ld_stage(sbase, 0, A0, A1, lda, m0, B0p, B1p, ldb, n0, 0, tid);
    CP_COMMIT();

    for (int kt = 0; kt < KT; kt++) {
        const int cur = kt & 1;
        CP_WAIT0();
        __syncthreads();
        if (kt + 1 < KT) {
            ld_stage(sbase, cur ^ 1, A0, A1, lda, m0, B0p, B1p, ldb, n0, (kt + 1) << 5, tid);
            CP_COMMIT();
        }
        const uint32_t bA0 = sbase + cur * STAGE_BYTES;
        const uint32_t bA1 = bA0 + TILE_BYTES;
        const uint32_t bB0 = bA0 + 2 * TILE_BYTES;
        const uint32_t bB1 = bA0 + 3 * TILE_BYTES;
#pragma unroll
        for (int kh = 0; kh < 2; kh++) {
            const int colh = kh * 16 + ((lane >> 4) & 1) * 8;
            uint32_t a0f[2][4], a1f[2][4];
#pragma unroll
            for (int mt = 0; mt < 2; mt++) {
                int row = wm * 32 + mt * 16 + (lane & 15);
                uint32_t off = (uint32_t)((row * SMPAD + colh) * 2);
                LDMX4(a0f[mt][0], a0f[mt][1], a0f[mt][2], a0f[mt][3], bA0 + off);
                LDMX4(a1f[mt][0], a1f[mt][1], a1f[mt][2], a1f[mt][3], bA1 + off);
            }
#pragma unroll
            for (int bt = 0; bt < 4; bt++) {
                int row = wn * 64 + bt * 16 + (lane & 15);
                uint32_t off = (uint32_t)((row * SMPAD + colh) * 2);
                uint32_t b0f[4], b1f[4];
                LDMX4(b0f[0], b0f[1], b0f[2], b0f[3], bB0 + off);
                LDMX4(b1f[0], b1f[1], b1f[2], b1f[3], bB1 + off);
#pragma unroll
                for (int mt = 0; mt < 2; mt++)
#pragma unroll
                    for (int hi = 0; hi < 2; hi++) {
                        int nt = bt * 2 + hi;
                        mma16816(accM[mt][nt], a0f[mt], b0f[hi], b0f[2 + hi]);
                        mma16816(accC[mt][nt], a0f[mt], b1f[hi], b1f[2 + hi]);
                        mma16816(accC[mt][nt], a1f[mt], b0f[hi], b0f[2 + hi]);
                    }
            }
        }
    }

    const float cs = 1.f / 2048.f;
    const int g = lane >> 2, q2 = (lane & 3) * 2;

    if (mode == 0) {
#pragma unroll
        for (int mt = 0; mt < 2; mt++) {
            int row = m0 + wm * 32 + mt * 16 + g;
#pragma unroll
            for (int nt = 0; nt < 8; nt++) {
                int col = n0 + wn * 64 + nt * 8 + q2;
                float2 bb = *(const float2*)(bias + col);
                float2 o0 = { accM[mt][nt][0] + accC[mt][nt][0] * cs + bb.x,
                              accM[mt][nt][1] + accC[mt][nt][1] * cs + bb.y };
                float2 o1 = { accM[mt][nt][2] + accC[mt][nt][2] * cs + bb.x,
                              accM[mt][nt][3] + accC[mt][nt][3] * cs + bb.y };
                *(float2*)(C + (size_t)row * ldc + col) = o0;
                *(float2*)(C + (size_t)(row + 8) * ldc + col) = o1;
            }
        }
    } else {
        // stage combined acc into smem (reuse pipeline buffers)
        __syncthreads();
        float* Cs = (float*)dsm;
#pragma unroll
        for (int mt = 0; mt < 2; mt++) {
            int row = wm * 32 + mt * 16 + g;
#pragma unroll
            for (int nt = 0; nt < 8; nt++) {
                int col = wn * 64 + nt * 8 + q2;
                Cs[row * CS_STRIDE + col]           = accM[mt][nt][0] + accC[mt][nt][0] * cs;
                Cs[row * CS_STRIDE + col + 1]       = accM[mt][nt][1] + accC[mt][nt][1] * cs;
                Cs[(row + 8) * CS_STRIDE + col]     = accM[mt][nt][2] + accC[mt][nt][2] * cs;
                Cs[(row + 8) * CS_STRIDE + col + 1] = accM[mt][nt][3] + accC[mt][nt][3] * cs;
            }
        }
        __syncthreads();
        const int ubase = n0 >> 2;   // 32 units per CTA col-tile (cols interleaved 4*u+gate)
#pragma unroll
        for (int i = 0; i < 16; i++) {
            int idx = tid + i * 256;         // 0..4095
            int b = idx >> 5, u = idx & 31;
            int tok = stok[b];
            float4 g4 = *(float4*)&Cs[b * CS_STRIDE + 4 * u];
            float4 t4 = *(const float4*)(Ts + (size_t)tok * G4H + n0 + 4 * u);
            float gi = g4.x + t4.x, gf = g4.y + t4.y, gg = g4.z + t4.z, go = g4.w + t4.w;
            int bg = m0 + b, j = ubase + u;
            size_t ci = (size_t)bg * H + j;
            float cc = cst[ci];
            float si = 1.f / (1.f + expf(-gi));
            float sf = 1.f / (1.f + expf(-gf));
            float so = 1.f / (1.f + expf(-go));
            float nc = sf * cc + si * tanhf(gg);
            cst[ci] = nc;
            float h = so * tanhf(nc);
            split2h(h, ho0[ci], ho1[ci]);
        }
    }
}

// ================= setup / elementwise kernels =================
__global__ void split2_kernel(const float* __restrict__ src, int n,
                              __half* __restrict__ p0, __half* __restrict__ p1)
{
    int i = blockIdx.x * blockDim.x + threadIdx.x;
    if (i < n) split2h(src[i], p0[i], p1[i]);
}

// interleaved concat weights: out row n -> (unit u=n>>2, gate g=n&3) = orig row g*H+u
__global__ void build_wc_int(const float* __restrict__ Wih, const float* __restrict__ Whh,
                             __half* __restrict__ p0, __half* __restrict__ p1)
{
    int idx = blockIdx.x * blockDim.x + threadIdx.x;
    if (idx >= G4H * KC) return;
    int n = idx / KC, k = idx % KC;
    int u = n >> 2, gg = n & 3;
    int orig = gg * H + u;
    float w = (k < E) ? Wih[orig * E + k] : Whh[orig * H + (k - E)];
    split2h(w, p0[idx], p1[idx]);
}

__global__ void bias_int(const float* __restrict__ bih, const float* __restrict__ bhh,
                         float* __restrict__ bc)
{
    int n = blockIdx.x * blockDim.x + threadIdx.x;
    if (n >= G4H) return;
    int u = n >> 2, gg = n & 3;
    int orig = gg * H + u;
    bc[n] = bih[orig] + bhh[orig];
}

__global__ void zero_f(float* p, int n)
{
    int i = blockIdx.x * blockDim.x + threadIdx.x;
    if (i < n) p[i] = 0.f;
}

__global__ void zero_h2(__half* p0, __half* p1, int n)
{
    int i = blockIdx.x * blockDim.x + threadIdx.x;
    if (i < n) { p0[i] = __float2half(0.f); p1[i] = __float2half(0.f); }
}

__global__ void build_nwc(const float* __restrict__ wc, float* __restrict__ nwc)
{
    __shared__ float red[1024];
    int t = threadIdx.x;
    float w = wc[t] * (t == BOUND ? 0.1f : 1.0f);
    red[t] = w;
    __syncthreads();
    for (int off = 512; off; off >>= 1) {
        if (t < off) red[t] += red[t + off];
        __syncthreads();
    }
    float denom = red[0];
    nwc[t] = (denom > 0.f) ? (w / denom) : w;
}

__global__ void init_sender(int* tok, int* sl, float* vl, int* m)
{
    int b = blockIdx.x * blockDim.x + threadIdx.x;
    if (b < B) {
        tok[b] = BOUND;
        sl[b] = LP1;
        vl[b] = 0.f;
        m[b * LP1] = BOUND;
    }
}

__global__ void h_split2(const float* __restrict__ hsrc,
                         __half* __restrict__ h0p, __half* __restrict__ h1p)
{
    int idx = blockIdx.x * blockDim.x + threadIdx.x;
    if (idx >= B * H) return;
    split2h(hsrc[idx], h0p[idx], h1p[idx]);
}

__global__ void score_step(const float* __restrict__ scores, const float* __restrict__ nwc,
                           int* tok, int* sl, float* vl, int* m, int step)
{
    __shared__ float sBest[256];
    __shared__ int   sIdx[256];
    __shared__ float sLM[256];
    __shared__ float sSum[256];
    int b = blockIdx.x, tid = threadIdx.x;
    const float* srow = scores + (size_t)b * V;

    float best = -1e30f; int bidx = 0; float lmax = -1e30f;
    for (int v = tid; v < V; v += 256) {
        float s = srow[v];
        if (s > best) { best = s; bidx = v; }
        float lg = s - nwc[v];
        lmax = fmaxf(lmax, lg);
    }
    sBest[tid] = best; sIdx[tid] = bidx; sLM[tid] = lmax;
    __syncthreads();
    for (int off = 128; off; off >>= 1) {
        if (tid < off) {
            float ob = sBest[tid + off]; int oi = sIdx[tid + off];
            if (ob > sBest[tid] || (ob == sBest[tid] && oi < sIdx[tid])) { sBest[tid] = ob; sIdx[tid] = oi; }
            sLM[tid] = fmaxf(sLM[tid], sLM[tid + off]);
        }
        __syncthreads();
    }
    float LM = sLM[0];
    int t = sIdx[0];
    __syncthreads();

    float ssum = 0.f;
    for (int v = tid; v < V; v += 256) ssum += expf(srow[v] - nwc[v] - LM);
    sSum[tid] = ssum;
    __syncthreads();
    for (int off = 128; off; off >>= 1) {
        if (tid < off) sSum[tid] += sSum[tid + off];
        __syncthreads();
    }
    if (tid == 0) {
        float ce = logf(sSum[0]) + LM - (srow[t] - nwc[t]);
        vl[b] += ce;
        tok[b] = t;
        if (t == BOUND && sl[b] == LP1) sl[b] = step + 2;
        m[b * LP1 + step + 1] = t;
    }
}

__global__ void pad_m(int* __restrict__ m, const int* __restrict__ sl)
{
    int idx = blockIdx.x * blockDim.x + threadIdx.x;
    if (idx >= B * LP1) return;
    int b = idx / LP1, pos = idx % LP1;
    if (pos >= sl[b]) m[idx] = BOUND;
}

__global__ void hist_m(const int* __restrict__ m, float* __restrict__ wcnt)
{
    int idx = blockIdx.x * blockDim.x + threadIdx.x;
    if (idx < B * LP1) atomicAdd(&wcnt[m[idx]], 1.0f);
}

__global__ void hinge_kernel(const float* __restrict__ target, const float* __restrict__ dis,
                             const float* __restrict__ r, const float* __restrict__ vl,
                             float* __restrict__ loss, float* __restrict__ acc)
{
    __shared__ float red[4][257];
    int b = blockIdx.x, t = threadIdx.x;
    const float* rr = r + (size_t)b * F;
    const float* tg = target + (size_t)b * F;
    float s0 = 0.f, s1 = 0.f, s2 = 0.f, s3 = 0.f;
    for (int f = t; f < F; f += 256) {
        float rv = rr[f];
        s0 += tg[f] * rv;
        s1 += dis[(size_t)0 * B * F + (size_t)b * F + f] * rv;
        s2 += dis[(size_t)1 * B * F + (size_t)b * F + f] * rv;
        s3 += dis[(size_t)2 * B * F + (size_t)b * F + f] * rv;
    }
    red[0][t] = s0; red[1][t] = s1; red[2][t] = s2; red[3][t] = s3;
    __syncthreads();
    for (int off = 128; off; off >>= 1) {
        if (t < off) {
#pragma unroll
            for (int q = 0; q < 4; q++) red[q][t] += red[q][t + off];
        }
        __syncthreads();
    }
    if (t == 0) {
        float ts = red[0][0], d0 = red[1][0], d1 = red[2][0], d2 = red[3][0];
        float lo = fmaxf(0.f, 1.f - ts + d0) + fmaxf(0.f, 1.f - ts + d1) + fmaxf(0.f, 1.f - ts + d2);
        loss[b] = lo + 0.1f * vl[b];
        acc[b] = (ts >= d0 && ts >= d1 && ts >= d2) ? 1.f : 0.f;
    }
}

__global__ void finalize(const float* __restrict__ loss, const float* __restrict__ acc, float* __restrict__ out)
{
    __shared__ float rl[1024], ra[1024];
    int t = threadIdx.x;
    float s = 0.f, a = 0.f;
    for (int i = t; i < B; i += 1024) { s += loss[i]; a += acc[i]; }
    rl[t] = s; ra[t] = a;
    __syncthreads();
    for (int off = 512; off; off >>= 1) {
        if (t < off) { rl[t] += rl[t + off]; ra[t] += ra[t + off]; }
        __syncthreads();
    }
    if (t == 0) { out[0] = rl[0] / (float)B; out[1] = ra[0] / (float)B; }
}

__global__ void write_m(const int* __restrict__ m, float* __restrict__ out)
{
    int idx = blockIdx.x * blockDim.x + threadIdx.x;
    if (idx < B * LP1) out[2 + idx] = (float)m[idx];
}

__global__ void write_wc(const float* __restrict__ wcnt, float* __restrict__ out)
{
    int v = blockIdx.x * blockDim.x + threadIdx.x;
    if (v < V) out[2 + B * LP1 + v] = wcnt[v];
}

// ================= launch =================
extern "C" void kernel_launch(void* const* d_in, const int* in_sizes, int n_in,
                              void* d_out, int out_size)
{
    const float* target = (const float*)d_in[0];
    const float* dis    = (const float*)d_in[1];
    const float* wcin   = (const float*)d_in[2];
    const float* emb_s  = (const float*)d_in[3];
    const float* affsW  = (const float*)d_in[4];
    const float* affsb  = (const float*)d_in[5];
    const float* Wih    = (const float*)d_in[6];
    const float* Whh    = (const float*)d_in[7];
    const float* bih    = (const float*)d_in[8];
    const float* bhh    = (const float*)d_in[9];
    const float* lpW    = (const float*)d_in[10];
    const float* lpb    = (const float*)d_in[11];
    const float* emb_r  = (const float*)d_in[12];
    const float* rWih   = (const float*)d_in[13];
    const float* rWhh   = (const float*)d_in[14];
    const float* rbih   = (const float*)d_in[15];
    const float* rbhh   = (const float*)d_in[16];
    const float* affrW  = (const float*)d_in[17];
    const float* affrb  = (const float*)d_in[18];
    float* out = (float*)d_out;

    static int smem_set = 0;
    cudaFuncSetAttribute(hmma3, cudaFuncAttributeMaxDynamicSharedMemorySize, DSM_BYTES);
    (void)smem_set;

    float *p_c, *p_gates, *p_scores, *p_vl, *p_nwc, *p_r, *p_loss, *p_acc, *p_wcnt;
    float *p_bc, *p_bcR, *p_Ts, *p_Tr;
    int *p_tok, *p_sl, *p_m;
    __half *h0[2], *h1[2], *W0p, *W1p, *R0p, *R1p, *L0p, *L1p, *S0p, *S1p, *A0p, *A1p;
    __half *T0p, *T1p, *E0p, *E1p, *Fe0p, *Fe1p;
    cudaGetSymbolAddress((void**)&p_c, g_c);
    cudaGetSymbolAddress((void**)&p_gates, g_gates);
    cudaGetSymbolAddress((void**)&p_scores, g_scores);
    cudaGetSymbolAddress((void**)&p_vl, g_vl);
    cudaGetSymbolAddress((void**)&p_nwc, g_nwc);
    cudaGetSymbolAddress((void**)&p_r, g_r);
    cudaGetSymbolAddress((void**)&p_loss, g_loss);
    cudaGetSymbolAddress((void**)&p_acc, g_acc);
    cudaGetSymbolAddress((void**)&p_wcnt, g_wcnt);
    cudaGetSymbolAddress((void**)&p_bc, g_bc);
    cudaGetSymbolAddress((void**)&p_bcR, g_bcR);
    cudaGetSymbolAddress((void**)&p_Ts, g_Ts);
    cudaGetSymbolAddress((void**)&p_Tr, g_Tr);
    cudaGetSymbolAddress((void**)&p_tok, g_tok);
    cudaGetSymbolAddress((void**)&p_sl, g_sl);
    cudaGetSymbolAddress((void**)&p_m, g_m);
    cudaGetSymbolAddress((void**)&h0[0], g_h0a); cudaGetSymbolAddress((void**)&h1[0], g_h1a);
    cudaGetSymbolAddress((void**)&h0[1], g_h0b); cudaGetSymbolAddress((void**)&h1[1], g_h1b);
    cudaGetSymbolAddress((void**)&W0p, g_W0p);  cudaGetSymbolAddress((void**)&W1p, g_W1p);
    cudaGetSymbolAddress((void**)&R0p, g_R0p);  cudaGetSymbolAddress((void**)&R1p, g_R1p);
    cudaGetSymbolAddress((void**)&L0p, g_L0p);  cudaGetSymbolAddress((void**)&L1p, g_L1p);
    cudaGetSymbolAddress((void**)&S0p, g_S0p);  cudaGetSymbolAddress((void**)&S1p, g_S1p);
    cudaGetSymbolAddress((void**)&A0p, g_A0p);  cudaGetSymbolAddress((void**)&A1p, g_A1p);
    cudaGetSymbolAddress((void**)&T0p, g_T0p);  cudaGetSymbolAddress((void**)&T1p, g_T1p);
    cudaGetSymbolAddress((void**)&E0p, g_E0p);  cudaGetSymbolAddress((void**)&E1p, g_E1p);
    cudaGetSymbolAddress((void**)&Fe0p, g_F0p); cudaGetSymbolAddress((void**)&Fe1p, g_F1p);

    const int BH = B * H;

    // ---- setup: splits + interleaved weights ----
    build_nwc<<<1, 1024>>>(wcin, p_nwc);
    bias_int<<<(G4H + 255) / 256, 256>>>(bih, bhh, p_bc);
    bias_int<<<(G4H + 255) / 256, 256>>>(rbih, rbhh, p_bcR);
    build_wc_int<<<(G4H * KC + 255) / 256, 256>>>(Wih, Whh, W0p, W1p);
    build_wc_int<<<(G4H * KC + 255) / 256, 256>>>(rWih, rWhh, R0p, R1p);
    split2_kernel<<<(V * H + 255) / 256, 256>>>(lpW, V * H, L0p, L1p);
    split2_kernel<<<(H * F + 255) / 256, 256>>>(affsW, H * F, S0p, S1p);
    split2_kernel<<<(F * H + 255) / 256, 256>>>(affrW, F * H, A0p, A1p);
    split2_kernel<<<(B * F + 255) / 256, 256>>>(target, B * F, T0p, T1p);
    split2_kernel<<<(V * E + 255) / 256, 256>>>(emb_s, V * E, E0p, E1p);
    split2_kernel<<<(V * E + 255) / 256, 256>>>(emb_r, V * E, Fe0p, Fe1p);
    zero_f<<<(BH + 255) / 256, 256>>>(p_c, BH);
    init_sender<<<(B + 255) / 256, 256>>>(p_tok, p_sl, p_vl, p_m);

    // ---- precompute token tables Ts/Tr = emb @ Wc^T + bias (step-invariant) ----
    hmma3<<<dim3(G4H / 128, V / 128), 256, DSM_BYTES>>>(
        E0p, E1p, E, W0p, W1p, KC, p_Ts, G4H, p_bc, E,
        0, nullptr, 0, nullptr, nullptr, nullptr, nullptr);
    hmma3<<<dim3(G4H / 128, V / 128), 256, DSM_BYTES>>>(
        Fe0p, Fe1p, E, R0p, R1p, KC, p_Tr, G4H, p_bcR, E,
        0, nullptr, 0, nullptr, nullptr, nullptr, nullptr);

    // ---- h0 = target @ aff_s_W^T + aff_s_b ----
    hmma3<<<dim3(H / 128, B / 128), 256, DSM_BYTES>>>(
        T0p, T1p, F, S0p, S1p, F, p_gates, H, affsb, F,
        0, nullptr, 0, nullptr, nullptr, nullptr, nullptr);
    h_split2<<<(BH + 255) / 256, 256>>>(p_gates, h0[0], h1[0]);

    // ---- sender loop (K=H only; emb part via Ts gather in epilogue) ----
    int cur = 0;
    for (int i = 0; i < L; i++) {
        hmma3<<<dim3(G4H / 128, B / 128), 256, DSM_BYTES>>>(
            h0[cur], h1[cur], H, W0p + E, W1p + E, KC, nullptr, 0, nullptr, H,
            1, p_tok, 1, p_Ts, p_c, h0[cur ^ 1], h1[cur ^ 1]);
        cur ^= 1;
        hmma3<<<dim3(V / 128, B / 128), 256, DSM_BYTES>>>(
            h0[cur], h1[cur], H, L0p, L1p, H, p_scores, V, lpb, H,
            0, nullptr, 0, nullptr, nullptr, nullptr, nullptr);
        score_step<<<B, 256>>>(p_scores, p_nwc, p_tok, p_sl, p_vl, p_m, i);
    }

    pad_m<<<(B * LP1 + 255) / 256, 256>>>(p_m, p_sl);
    zero_f<<<(V + 255) / 256, 256>>>(p_wcnt, V);
    hist_m<<<(B * LP1 + 255) / 256, 256>>>(p_m, p_wcnt);

    // ---- receiver ----
    zero_f<<<(BH + 255) / 256, 256>>>(p_c, BH);
    zero_h2<<<(BH + 255) / 256, 256>>>(h0[cur], h1[cur], BH);
    for (int t = 0; t < LP1; t++) {
        hmma3<<<dim3(G4H / 128, B / 128), 256, DSM_BYTES>>>(
            h0[cur], h1[cur], H, R0p + E, R1p + E, KC, nullptr, 0, nullptr, H,
            1, p_m + t, LP1, p_Tr, p_c, h0[cur ^ 1], h1[cur ^ 1]);
        cur ^= 1;
    }

    // ---- r = hr @ aff_r_W^T + aff_r_b ----
    hmma3<<<dim3(F / 128, B / 128), 256, DSM_BYTES>>>(
        h0[cur], h1[cur], H, A0p, A1p, H, p_r, F, affrb, H,
        0, nullptr, 0, nullptr, nullptr, nullptr, nullptr);

    hinge_kernel<<<B, 256>>>(target, dis, p_r, p_vl, p_loss, p_acc);
    finalize<<<1, 1024>>>(p_loss, p_acc, out);
    write_m<<<(B * LP1 + 255) / 256, 256>>>(p_m, out);
    write_wc<<<(V + 255) / 256, 256>>>(p_wcnt, out);
}